// round 3
// baseline (speedup 1.0000x reference)
#include <cuda_runtime.h>
#include <cuda_bf16.h>

// Problem constants (fixed by the reference)
#define NN 32768
#define DD 32
#define HH 64
#define TT 1024
#define MM 8
#define SS 2177          // H*D + H + O*H + O = 2048+64+64+1
#define SROW 2208        // padded row stride (multiple of 32 floats, 128B-aligned)
#define CAP 128          // bucket capacity (mean 32, +17 sigma)

// Scratch (no allocations allowed in kernel_launch)
__device__ float g_states[TT * SROW];      // ~9.0 MB state table
__device__ int   g_cnt[TT];
__device__ int   g_bucket[TT * CAP];
__device__ int   g_ocnt;
__device__ int   g_ovf[NN];

// ---------------------------------------------------------------------------
// Zero the per-call counters (kernel so it's trivially graph-capturable)
// ---------------------------------------------------------------------------
__global__ void zero_k() {
    int i = blockIdx.x * blockDim.x + threadIdx.x;
    if (i < TT) g_cnt[i] = 0;
    if (i == TT) g_ocnt = 0;
}

// ---------------------------------------------------------------------------
// states[t][s] = base[s] + bias[s] + sum_m mesa[m][t] * meta[s][m]
// ---------------------------------------------------------------------------
__global__ void states_k(const float* __restrict__ mesa,
                         const float* __restrict__ meta,
                         const float* __restrict__ bias,
                         const float* __restrict__ base) {
    int s = blockIdx.x * 256 + threadIdx.x;
    int t = blockIdx.y;
    if (s >= SS) return;
    float acc = base[s] + bias[s];
#pragma unroll
    for (int m = 0; m < MM; m++)
        acc = fmaf(mesa[m * TT + t], meta[s * MM + m], acc);
    g_states[t * SROW + s] = acc;
}

// ---------------------------------------------------------------------------
// Bucket n-indices by ticker value (overflow -> slow-path list)
// ---------------------------------------------------------------------------
__global__ void scatter_k(const int* __restrict__ ticker) {
    int n = blockIdx.x * blockDim.x + threadIdx.x;
    if (n >= NN) return;
    int t = ticker[n];
    int pos = atomicAdd(&g_cnt[t], 1);
    if (pos < CAP) {
        g_bucket[t * CAP + pos] = n;
    } else {
        int o = atomicAdd(&g_ocnt, 1);
        g_ovf[o] = n;
    }
}

// ---------------------------------------------------------------------------
// Main compute: one block per t. w1[t] cached in registers (lane l owns
// rows l and l+32). One warp per sample n; x broadcast via shfl.
// ---------------------------------------------------------------------------
__global__ __launch_bounds__(256, 2) void main_k(const float* __restrict__ x,
                                                 float* __restrict__ out) {
    int t = blockIdx.x;
    const float* row = g_states + t * SROW;

    __shared__ float w1p[HH * 33];   // padded: conflict-free strided reads
    __shared__ float b1s[HH];
    __shared__ float w2s[HH];
    __shared__ float b2sh;

    // Stage w1 coalesced gmem -> padded smem
    for (int i = threadIdx.x; i < HH * DD; i += 256)
        w1p[(i >> 5) * 33 + (i & 31)] = row[i];
    if (threadIdx.x < 64)       b1s[threadIdx.x]      = row[2048 + threadIdx.x];
    else if (threadIdx.x < 128) w2s[threadIdx.x - 64] = row[2048 + threadIdx.x]; // s=2112..2175
    else if (threadIdx.x == 128) b2sh = row[2176];
    __syncthreads();

    int lane = threadIdx.x & 31;
    int warp = threadIdx.x >> 5;

    // Each lane owns two w1 rows in registers (64 regs)
    float wA[DD], wB[DD];
#pragma unroll
    for (int d = 0; d < DD; d++) {
        wA[d] = w1p[lane * 33 + d];
        wB[d] = w1p[(lane + 32) * 33 + d];
    }
    float b1A = b1s[lane], b1B = b1s[lane + 32];
    float w2A = w2s[lane], w2B = w2s[lane + 32];
    float b2v = b2sh;

    int cnt = g_cnt[t];
    if (cnt > CAP) cnt = CAP;

    for (int i = warp; i < cnt; i += 8) {
        int n = g_bucket[t * CAP + i];
        float xr = x[n * DD + lane];          // one coalesced 128B line
        float a0 = 0.f, a1 = 0.f;
#pragma unroll
        for (int d = 0; d < DD; d++) {
            float xv = __shfl_sync(0xffffffffu, xr, d);
            a0 = fmaf(wA[d], xv, a0);
            a1 = fmaf(wB[d], xv, a1);
        }
        float h0 = fmaxf(a0 + b1A, 0.f);
        float h1 = fmaxf(a1 + b1B, 0.f);
        float p = fmaf(h0, w2A, h1 * w2B);
#pragma unroll
        for (int off = 16; off; off >>= 1)
            p += __shfl_down_sync(0xffffffffu, p, off);
        if (lane == 0) out[n] = p + b2v;
    }
}

// ---------------------------------------------------------------------------
// Overflow slow path (normally processes 0 elements; correctness insurance)
// ---------------------------------------------------------------------------
__global__ void overflow_k(const int* __restrict__ ticker,
                           const float* __restrict__ x,
                           float* __restrict__ out) {
    int i = blockIdx.x * blockDim.x + threadIdx.x;
    if (i >= g_ocnt) return;
    int n = g_ovf[i];
    int t = ticker[n];
    const float* row = g_states + t * SROW;
    float o = row[2176];
    for (int j = 0; j < HH; j++) {
        float a = row[2048 + j];
        for (int d = 0; d < DD; d++)
            a = fmaf(row[j * DD + d], x[n * DD + d], a);
        o = fmaf(fmaxf(a, 0.f), row[2112 + j], o);
    }
    out[n] = o;
}

// ---------------------------------------------------------------------------
extern "C" void kernel_launch(void* const* d_in, const int* in_sizes, int n_in,
                              void* d_out, int out_size) {
    const float* x      = (const float*)d_in[0];
    const int*   ticker = (const int*)d_in[1];
    const float* mesa   = (const float*)d_in[2];
    const float* meta   = (const float*)d_in[3];
    const float* bias   = (const float*)d_in[4];
    const float* base   = (const float*)d_in[5];
    float* out = (float*)d_out;

    zero_k<<<5, 256>>>();
    states_k<<<dim3((SS + 255) / 256, TT), 256>>>(mesa, meta, bias, base);
    scatter_k<<<(NN + 255) / 256, 256>>>(ticker);
    main_k<<<TT, 256>>>(x, out);
    overflow_k<<<(NN + 255) / 256, 256>>>(ticker, x, out);
}

// round 4
// speedup vs baseline: 1.1873x; 1.1873x over previous
#include <cuda_runtime.h>

// Problem constants (fixed by the reference)
#define NN 32768
#define DD 32
#define HH 64
#define TT 1024
#define MM 8
#define SS 2177          // H*D + H + O*H + O
#define SROW 2208        // padded state row stride (floats)
#define CAP 128          // bucket capacity (Poisson(32); P(>128) ~ 0)
#define XSTR 36          // x-stage row stride: conflict-free LDS.128 at 144B

// Scratch (no allocations allowed)
__device__ float g_states[TT * SROW];
__device__ int   g_cnt[TT];
__device__ int   g_bucket[TT * CAP];
__device__ int   g_ocnt;
__device__ int   g_ovf[NN];

// packed fp32x2 FMA (Blackwell; ptxas never auto-fuses this)
#define FMA2(d, a, b, c) \
    asm("fma.rn.f32x2 %0, %1, %2, %3;" : "=l"(d) : "l"(a), "l"(b), "l"(c))

// ---------------------------------------------------------------------------
// states[t][s] = base[s] + bias[s] + sum_m mesa[m][t] * meta[s][m]
// Also zeroes the bucket counters (runs before scatter_k in stream order).
// ---------------------------------------------------------------------------
__global__ void states_k(const float* __restrict__ mesa,
                         const float* __restrict__ meta,
                         const float* __restrict__ bias,
                         const float* __restrict__ base) {
    int t = blockIdx.y;
    if (blockIdx.x == 0 && threadIdx.x == 0) {
        g_cnt[t] = 0;
        if (t == 0) g_ocnt = 0;
    }
    int s = blockIdx.x * 256 + threadIdx.x;
    if (s >= SS) return;
    float acc = base[s] + bias[s];
#pragma unroll
    for (int m = 0; m < MM; m++)
        acc = fmaf(mesa[m * TT + t], meta[s * MM + m], acc);
    g_states[t * SROW + s] = acc;
}

// ---------------------------------------------------------------------------
// Bucket n-indices by ticker value (overflow -> slow-path list)
// ---------------------------------------------------------------------------
__global__ void scatter_k(const int* __restrict__ ticker) {
    int n = blockIdx.x * blockDim.x + threadIdx.x;
    if (n >= NN) return;
    int t = ticker[n];
    int pos = atomicAdd(&g_cnt[t], 1);
    if (pos < CAP) {
        g_bucket[t * CAP + pos] = n;
    } else {
        int o = atomicAdd(&g_ocnt, 1);
        g_ovf[o] = n;
    }
}

// ---------------------------------------------------------------------------
// Main compute. Block = 512 threads = 16 warps = 8 t's (2 warps per t).
// Lane l processes sample l of a 32-sample chunk: weights broadcast from
// smem, x rows transposed through smem, accumulation fully per-lane
// (no shfl, no reduction). Inner product uses packed f32x2 FMA.
// ---------------------------------------------------------------------------
__global__ __launch_bounds__(512, 1) void main_k(const float* __restrict__ x,
                                                 float* __restrict__ out) {
    extern __shared__ float sm[];
    float* st = sm;                   // 8 * SROW floats
    float* xs = sm + 8 * SROW;        // 16 * 32 * XSTR floats

    int tid  = threadIdx.x;
    int warp = tid >> 5, lane = tid & 31;
    int tl   = warp >> 1, half = warp & 1;
    int t    = blockIdx.x * 8 + tl;

    // Stage this t's state row (warp pair cooperates, float4 coalesced)
    {
        const float4* src = (const float4*)(g_states + t * SROW);
        float4*       dst = (float4*)(st + tl * SROW);
        for (int i = half * 32 + lane; i < SROW / 4; i += 64)
            dst[i] = src[i];
    }
    __syncthreads();

    const float* w1 = st + tl * SROW;
    const float* b1 = w1 + 2048;
    const float* w2 = w1 + 2112;
    float b2v = w1[2176];
    float* myxs = xs + warp * (32 * XSTR);

    int cnt = g_cnt[t];
    if (cnt > CAP) cnt = CAP;
    const int* bk = g_bucket + t * CAP;

    for (int base = half * 32; base < cnt; base += 64) {
        int m = cnt - base;
        if (m > 32) m = 32;
        int n = (lane < m) ? bk[base + lane] : 0;

        // Transpose-stage x rows: 32 coalesced 128B loads instead of
        // 256 scattered wavefronts.
        for (int s2 = 0; s2 < m; s2++) {
            int ns = __shfl_sync(0xffffffffu, n, s2);
            myxs[s2 * XSTR + lane] = x[ns * DD + lane];
        }
        __syncwarp();

        // My x row -> 16 packed f32x2 registers (stride-36 = conflict-free)
        unsigned long long x2[16];
        {
            const ulonglong2* xr = (const ulonglong2*)(myxs + lane * XSTR);
#pragma unroll
            for (int k = 0; k < 8; k++) {
                ulonglong2 v = xr[k];
                x2[2 * k]     = v.x;
                x2[2 * k + 1] = v.y;
            }
        }

        float o = 0.f;
#pragma unroll 4
        for (int j = 0; j < HH; j++) {
            const ulonglong2* wr = (const ulonglong2*)(w1 + j * DD);
            unsigned long long accA = 0ull, accB = 0ull;   // (0.f, 0.f)
#pragma unroll
            for (int k = 0; k < 8; k++) {
                ulonglong2 w = wr[k];                       // broadcast LDS
                FMA2(accA, x2[2 * k],     w.x, accA);
                FMA2(accB, x2[2 * k + 1], w.y, accB);
            }
            float a0, a1, c0, c1;
            asm("mov.b64 {%0,%1}, %2;" : "=f"(a0), "=f"(a1) : "l"(accA));
            asm("mov.b64 {%0,%1}, %2;" : "=f"(c0), "=f"(c1) : "l"(accB));
            float h = (a0 + a1) + (c0 + c1) + b1[j];
            h = fmaxf(h, 0.f);
            o = fmaf(h, w2[j], o);
        }
        if (lane < m) out[n] = o + b2v;
        __syncwarp();
    }
}

// ---------------------------------------------------------------------------
// Overflow slow path (normally 0 elements; correctness insurance)
// ---------------------------------------------------------------------------
__global__ void overflow_k(const int* __restrict__ ticker,
                           const float* __restrict__ x,
                           float* __restrict__ out) {
    int i = blockIdx.x * blockDim.x + threadIdx.x;
    if (i >= g_ocnt) return;
    int n = g_ovf[i];
    int t = ticker[n];
    const float* row = g_states + t * SROW;
    float o = row[2176];
    for (int j = 0; j < HH; j++) {
        float a = row[2048 + j];
        for (int d = 0; d < DD; d++)
            a = fmaf(row[j * DD + d], x[n * DD + d], a);
        o = fmaf(fmaxf(a, 0.f), row[2112 + j], o);
    }
    out[n] = o;
}

// ---------------------------------------------------------------------------
extern "C" void kernel_launch(void* const* d_in, const int* in_sizes, int n_in,
                              void* d_out, int out_size) {
    const float* x      = (const float*)d_in[0];
    const int*   ticker = (const int*)d_in[1];
    const float* mesa   = (const float*)d_in[2];
    const float* meta   = (const float*)d_in[3];
    const float* bias   = (const float*)d_in[4];
    const float* base   = (const float*)d_in[5];
    float* out = (float*)d_out;

    const int smem_bytes = (8 * SROW + 16 * 32 * XSTR) * sizeof(float); // 141KB
    cudaFuncSetAttribute(main_k, cudaFuncAttributeMaxDynamicSharedMemorySize,
                         smem_bytes);

    states_k<<<dim3((SS + 255) / 256, TT), 256>>>(mesa, meta, bias, base);
    scatter_k<<<(NN + 255) / 256, 256>>>(ticker);
    main_k<<<TT / 8, 512, smem_bytes>>>(x, out);
    overflow_k<<<(NN + 255) / 256, 256>>>(ticker, x, out);
}

// round 5
// speedup vs baseline: 1.9835x; 1.6706x over previous
#include <cuda_runtime.h>

// Problem constants (fixed by the reference)
#define NN 32768
#define DD 32
#define HH 64
#define TT 1024
#define MM 8
#define SS 2177          // H*D + H + O*H + O
#define SROW 2208        // padded state row stride (floats)
#define CAP 128          // bucket capacity (Poisson(32); P(>128) ~ 0)
#define CT  64           // t-tile for states_k

// Scratch (no allocations allowed)
__device__ float g_states[TT * SROW];
__device__ int   g_cnt[TT];
__device__ int   g_bucket[TT * CAP];
__device__ int   g_ocnt;
__device__ int   g_ovf[NN];

// packed fp32x2 FMA (Blackwell; ptxas never auto-fuses this)
#define FMA2(d, a, b, c) \
    asm("fma.rn.f32x2 %0, %1, %2, %3;" : "=l"(d) : "l"(a), "l"(b), "l"(c))
#define PACK2(d, lo, hi) \
    asm("mov.b64 %0, {%1, %2};" : "=l"(d) : "f"(lo), "f"(hi))
#define UNPACK2(lo, hi, s) \
    asm("mov.b64 {%0, %1}, %2;" : "=f"(lo), "=f"(hi) : "l"(s))

// ---------------------------------------------------------------------------
// states[t][s] = base[s] + bias[s] + sum_m mesa[m][t] * meta[s][m]
// Tiled over t (CT per block) so meta is read 16x total, not 1024x.
// Also zeroes the bucket counters (stream order: before scatter_k).
// ---------------------------------------------------------------------------
__global__ void states_k(const float* __restrict__ mesa,
                         const float* __restrict__ meta,
                         const float* __restrict__ bias,
                         const float* __restrict__ base) {
    __shared__ float sm_mesa[MM][CT];
    int t0 = blockIdx.y * CT;

    if (blockIdx.x == 0) {
        if (threadIdx.x < CT) g_cnt[t0 + threadIdx.x] = 0;
        if (blockIdx.y == 0 && threadIdx.x == CT) g_ocnt = 0;
    }

    for (int i = threadIdx.x; i < MM * CT; i += 256) {
        int m = i / CT, j = i % CT;
        sm_mesa[m][j] = mesa[m * TT + t0 + j];
    }
    __syncthreads();

    int s = blockIdx.x * 256 + threadIdx.x;
    if (s >= SS) return;

    float mt[MM];
#pragma unroll
    for (int m = 0; m < MM; m++) mt[m] = meta[s * MM + m];
    float bb = base[s] + bias[s];

#pragma unroll 4
    for (int j = 0; j < CT; j++) {
        float acc = bb;
#pragma unroll
        for (int m = 0; m < MM; m++)
            acc = fmaf(sm_mesa[m][j], mt[m], acc);
        g_states[(t0 + j) * SROW + s] = acc;   // coalesced per warp
    }
}

// ---------------------------------------------------------------------------
// Bucket n-indices by ticker value (overflow -> slow-path list)
// ---------------------------------------------------------------------------
__global__ void scatter_k(const int* __restrict__ ticker) {
    int n = blockIdx.x * blockDim.x + threadIdx.x;
    if (n >= NN) return;
    int t = ticker[n];
    int pos = atomicAdd(&g_cnt[t], 1);
    if (pos < CAP) {
        g_bucket[t * CAP + pos] = n;
    } else {
        int o = atomicAdd(&g_ocnt, 1);
        g_ovf[o] = n;
    }
}

// ---------------------------------------------------------------------------
// Main compute. Block = 256 threads = 8 warps = 8 t's (one warp per t).
// Lane l processes sample l of a 32-sample chunk. x rows loaded DIRECTLY
// per-lane as 8x LDG.128 (MLP=8, no serial staging chain). Weights broadcast
// from smem; each warp stages its own state row -> no block barrier at all.
// Inner product uses packed f32x2 FMA (2 MACs/instr).
// ---------------------------------------------------------------------------
__global__ __launch_bounds__(256, 1) void main_k(const float* __restrict__ x,
                                                 float* __restrict__ out) {
    extern __shared__ float st[];     // 8 * SROW floats = 70.6 KB

    int tid  = threadIdx.x;
    int warp = tid >> 5, lane = tid & 31;
    int t    = blockIdx.x * 8 + warp;

    // Warp stages its own state row (float4 coalesced, warp-local)
    float* myst = st + warp * SROW;
    {
        const float4* src = (const float4*)(g_states + t * SROW);
        float4*       dst = (float4*)myst;
#pragma unroll
        for (int k = 0; k < 18; k++) {
            int i = k * 32 + lane;
            if (i < SROW / 4) dst[i] = src[i];
        }
    }
    __syncwarp();

    const float* w1 = myst;
    const float* b1 = myst + 2048;
    const float* w2 = myst + 2112;
    float b2v = myst[2176];

    int cnt = g_cnt[t];
    if (cnt > CAP) cnt = CAP;
    const int* bk = g_bucket + t * CAP;

    for (int base = 0; base < cnt; base += 32) {
        int m = cnt - base;
        if (m > 32) m = 32;
        int li = lane < m ? lane : 0;          // clamp to a valid entry
        int n = bk[base + li];

        // Direct per-lane x row: 8 independent LDG.128 (MLP=8)
        unsigned long long x2[16];
        {
            const float4* xp = (const float4*)(x + (size_t)n * DD);
#pragma unroll
            for (int k = 0; k < 8; k++) {
                float4 v = xp[k];
                PACK2(x2[2 * k],     v.x, v.y);
                PACK2(x2[2 * k + 1], v.z, v.w);
            }
        }

        float o = 0.f;
#pragma unroll 8
        for (int j = 0; j < HH; j++) {
            const ulonglong2* wr = (const ulonglong2*)(w1 + j * DD);
            unsigned long long accA = 0ull, accB = 0ull;
#pragma unroll
            for (int k = 0; k < 8; k++) {
                ulonglong2 w = wr[k];          // broadcast LDS.128
                FMA2(accA, x2[2 * k],     w.x, accA);
                FMA2(accB, x2[2 * k + 1], w.y, accB);
            }
            float a0, a1, c0, c1;
            UNPACK2(a0, a1, accA);
            UNPACK2(c0, c1, accB);
            float h = (a0 + a1) + (c0 + c1) + b1[j];
            h = fmaxf(h, 0.f);
            o = fmaf(h, w2[j], o);
        }
        if (lane < m) out[n] = o + b2v;
    }
}

// ---------------------------------------------------------------------------
// Overflow slow path: single block, exits immediately when g_ocnt == 0
// (one LDG + branch; no 128-block grid drain like before).
// ---------------------------------------------------------------------------
__global__ void overflow_k(const int* __restrict__ ticker,
                           const float* __restrict__ x,
                           float* __restrict__ out) {
    int oc = g_ocnt;
    for (int i = threadIdx.x; i < oc; i += 256) {
        int n = g_ovf[i];
        int t = ticker[n];
        const float* row = g_states + t * SROW;
        float o = row[2176];
        for (int j = 0; j < HH; j++) {
            float a = row[2048 + j];
            for (int d = 0; d < DD; d++)
                a = fmaf(row[j * DD + d], x[n * DD + d], a);
            o = fmaf(fmaxf(a, 0.f), row[2112 + j], o);
        }
        out[n] = o;
    }
}

// ---------------------------------------------------------------------------
extern "C" void kernel_launch(void* const* d_in, const int* in_sizes, int n_in,
                              void* d_out, int out_size) {
    const float* x      = (const float*)d_in[0];
    const int*   ticker = (const int*)d_in[1];
    const float* mesa   = (const float*)d_in[2];
    const float* meta   = (const float*)d_in[3];
    const float* bias   = (const float*)d_in[4];
    const float* base   = (const float*)d_in[5];
    float* out = (float*)d_out;

    const int smem_bytes = 8 * SROW * sizeof(float);   // 70,656 B
    cudaFuncSetAttribute(main_k, cudaFuncAttributeMaxDynamicSharedMemorySize,
                         smem_bytes);

    states_k<<<dim3((SS + 255) / 256, TT / CT), 256>>>(mesa, meta, bias, base);
    scatter_k<<<(NN + 255) / 256, 256>>>(ticker);
    main_k<<<TT / 8, 256, smem_bytes>>>(x, out);
    overflow_k<<<1, 256>>>(ticker, x, out);   // 1 block; no-op when empty
}